// round 17
// baseline (speedup 1.0000x reference)
#include <cuda_runtime.h>
#include <cuda_fp16.h>
#include <cstdint>

#define DI __device__ __forceinline__

// Problem shape (fixed by the dataset)
static constexpr int M_TOTAL = 8192;   // B*S = 4*2048
static constexpr int N_TOTAL = 4096;
static constexpr int K_TOTAL = 1024;

// Row split: HMMA warps handle rows [0, M_H); the per-CTA dp4a sidecar warp
// handles rows [M_H, 8192) using exact int32 accumulation.
static constexpr int M_H     = 7424;               // 58 m-tiles
static constexpr int M_D     = M_TOTAL - M_H;      // 768 rows

// fp16 image for HMMA (int8 exact in fp16; fp32 acc exact, |acc| < 2^24)
__device__ __align__(16) uint16_t g_xh[(size_t)M_TOTAL * K_TOTAL];   // 16 MB
__device__ __align__(16) uint16_t g_wh[(size_t)N_TOTAL * K_TOTAL];   // 8 MB
// int8 images for the dp4a sidecar (w full; x only the dp4a row tail)
__device__ __align__(16) int8_t   g_w8[(size_t)N_TOTAL * K_TOTAL];   // 4 MB
__device__ __align__(16) int8_t   g_x8t[(size_t)M_D * K_TOTAL];      // 0.75 MB

// Tiling: CTA 128x128, warps 0-7 HMMA (4M x 2N, 32x64 warp tiles), warp 8 dp4a.
static constexpr int TILE_M  = 128;
static constexpr int TILE_N  = 128;
static constexpr int KSTAGE  = 64;                   // K elems per stage
static constexpr int NCHUNK  = K_TOTAL / KSTAGE;     // 16
static constexpr int NSTAGES = 3;
static constexpr int THREADS = 288;                  // 9 warps
static constexpr int LOADERS = 256;                  // threads doing cp.async
static constexpr int GRID_X  = N_TOTAL / TILE_N;     // 32
static constexpr int GRID_Y  = M_H / TILE_M;         // 58
static constexpr int NCTAS   = GRID_X * GRID_Y;      // 1856

// dp4a tiles: 32 cols x 4 rows, full K.  (4096/32)*(768/4) = 128*192 = 24576.
static constexpr int DP_CT   = N_TOTAL / 32;         // 128 col-tiles
static constexpr int DP_TILES = DP_CT * (M_D / 4);   // 24576 (<= 16 slices/CTA)

// SMEM: fp16 tiles, rows padded 128B -> 144B (conflict-free ldmatrix)
static constexpr int ROW_B   = 144;
static constexpr int A_STAGE = TILE_M * ROW_B;       // 18432 B
static constexpr int B_STAGE = TILE_N * ROW_B;       // 18432 B
static constexpr int SM_B0   = NSTAGES * A_STAGE;
static constexpr int SM_BYTES = NSTAGES * (A_STAGE + B_STAGE);  // 110592 B

DI uint32_t smem_u32(const void* p) {
    uint32_t a;
    asm("{ .reg .u64 t; cvta.to.shared.u64 t, %1; cvt.u32.u64 %0, t; }" : "=r"(a) : "l"(p));
    return a;
}
DI void cp16(uint32_t dst, const void* src) {
    asm volatile("cp.async.cg.shared.global [%0], [%1], 16;" :: "r"(dst), "l"(src));
}
#define CP_COMMIT() asm volatile("cp.async.commit_group;" ::: "memory")
#define CP_WAIT1()  asm volatile("cp.async.wait_group 1;" ::: "memory")

#define LDSM4(r0, r1, r2, r3, addr) \
    asm volatile("ldmatrix.sync.aligned.m8n8.x4.shared.b16 {%0,%1,%2,%3}, [%4];" \
                 : "=r"(r0), "=r"(r1), "=r"(r2), "=r"(r3) : "r"(addr))

#define MMA_F16(c, a0, a1, a2, a3, b0, b1) \
    asm volatile( \
        "mma.sync.aligned.m16n8k16.row.col.f32.f16.f16.f32 " \
        "{%0,%1,%2,%3}, {%4,%5,%6,%7}, {%8,%9}, {%0,%1,%2,%3};" \
        : "+f"((c)[0]), "+f"((c)[1]), "+f"((c)[2]), "+f"((c)[3]) \
        : "r"(a0), "r"(a1), "r"(a2), "r"(a3), "r"(b0), "r"(b1))

// ---------------- Pack pre-pass: int32 -> fp16 (+ int8 images) ----------------
DI uint32_t f16x2_from_ints(int lo, int hi) {
    __half2 h = __floats2half2_rn((float)lo, (float)hi);
    return *reinterpret_cast<uint32_t*>(&h);
}
DI uint4 pack8h(int4 v0, int4 v1) {
    uint4 o;
    o.x = f16x2_from_ints(v0.x, v0.y);
    o.y = f16x2_from_ints(v0.z, v0.w);
    o.z = f16x2_from_ints(v1.x, v1.y);
    o.w = f16x2_from_ints(v1.z, v1.w);
    return o;
}
DI uint32_t pack4b(int4 v) {
    return (uint32_t)(v.x & 0xFF) | ((uint32_t)(v.y & 0xFF) << 8) |
           ((uint32_t)(v.z & 0xFF) << 16) | ((uint32_t)v.w << 24);
}
__global__ void pack_both(const int4* __restrict__ xs, const int4* __restrict__ ws,
                          uint16_t* __restrict__ xd, uint16_t* __restrict__ wd,
                          int8_t* __restrict__ w8, int8_t* __restrict__ x8t,
                          int n8x, int n8w) {
    int i = blockIdx.x * blockDim.x + threadIdx.x;
    if (i < n8w) {
        int4 v0 = ws[(size_t)i * 2 + 0];
        int4 v1 = ws[(size_t)i * 2 + 1];
        reinterpret_cast<uint4*>(wd)[i] = pack8h(v0, v1);
        uint2 o8; o8.x = pack4b(v0); o8.y = pack4b(v1);
        reinterpret_cast<uint2*>(w8)[i] = o8;
    } else if (i - n8w < n8x) {
        int j = i - n8w;
        int4 v0 = xs[(size_t)j * 2 + 0];
        int4 v1 = xs[(size_t)j * 2 + 1];
        reinterpret_cast<uint4*>(xd)[j] = pack8h(v0, v1);
        const int j0 = (M_H * K_TOTAL) / 8;          // first group of dp4a tail
        if (j >= j0) {
            uint2 o8; o8.x = pack4b(v0); o8.y = pack4b(v1);
            reinterpret_cast<uint2*>(x8t)[j - j0] = o8;
        }
    }
}

// Load one K-stage: A 128 rows + B 128 rows, 128B/row, via cp.async (first 256 threads).
DI void load_stage(const uint16_t* __restrict__ x, const uint16_t* __restrict__ w,
                   int m0, int n0, int kc, uint32_t sbase, int stage, int tid) {
    if (tid >= LOADERS) return;
    const uint32_t smA = sbase + stage * A_STAGE;
    const uint32_t smB = sbase + SM_B0 + stage * B_STAGE;
    const int k0 = kc * KSTAGE;
#pragma unroll
    for (int i = 0; i < 4; i++) {
        int u = tid + i * LOADERS;
        int row = u >> 3, c = u & 7;
        cp16(smA + row * ROW_B + c * 16, x + (size_t)(m0 + row) * K_TOTAL + k0 + c * 8);
    }
#pragma unroll
    for (int i = 0; i < 4; i++) {
        int u = tid + i * LOADERS;
        int row = u >> 3, c = u & 7;
        cp16(smB + row * ROW_B + c * 16, w + (size_t)(n0 + row) * K_TOTAL + k0 + c * 8);
    }
}

// dp4a sidecar: one 32col x 4row tile, full K, exact int32 accumulation.
DI void dp4a_tile(int t, int lane, float si,
                  const float* __restrict__ scale_w, const float* __restrict__ bias,
                  float* __restrict__ out) {
    const int ct = t & (DP_CT - 1);
    const int rt = t >> 7;                           // / DP_CT
    const int n  = ct * 32 + lane;
    const int8_t* wrow = g_w8 + (size_t)n * K_TOTAL;
    const int8_t* xrow = g_x8t + (size_t)(rt * 4) * K_TOTAL;
    int a0 = 0, a1 = 0, a2 = 0, a3 = 0;
#pragma unroll 4
    for (int k = 0; k < K_TOTAL; k += 16) {
        int4 wv = *reinterpret_cast<const int4*>(wrow + k);
        int4 x0 = *reinterpret_cast<const int4*>(xrow + k);                // bcast
        int4 x1 = *reinterpret_cast<const int4*>(xrow + K_TOTAL + k);
        int4 x2 = *reinterpret_cast<const int4*>(xrow + 2 * K_TOTAL + k);
        int4 x3 = *reinterpret_cast<const int4*>(xrow + 3 * K_TOTAL + k);
        a0 = __dp4a(x0.x, wv.x, a0); a0 = __dp4a(x0.y, wv.y, a0);
        a0 = __dp4a(x0.z, wv.z, a0); a0 = __dp4a(x0.w, wv.w, a0);
        a1 = __dp4a(x1.x, wv.x, a1); a1 = __dp4a(x1.y, wv.y, a1);
        a1 = __dp4a(x1.z, wv.z, a1); a1 = __dp4a(x1.w, wv.w, a1);
        a2 = __dp4a(x2.x, wv.x, a2); a2 = __dp4a(x2.y, wv.y, a2);
        a2 = __dp4a(x2.z, wv.z, a2); a2 = __dp4a(x2.w, wv.w, a2);
        a3 = __dp4a(x3.x, wv.x, a3); a3 = __dp4a(x3.y, wv.y, a3);
        a3 = __dp4a(x3.z, wv.z, a3); a3 = __dp4a(x3.w, wv.w, a3);
    }
    const float s = si * __ldg(scale_w + n);
    const float b = __ldg(bias + n);
    const int r0 = M_H + rt * 4;
    out[(size_t)(r0 + 0) * N_TOTAL + n] = fmaf((float)a0, s, b);
    out[(size_t)(r0 + 1) * N_TOTAL + n] = fmaf((float)a1, s, b);
    out[(size_t)(r0 + 2) * N_TOTAL + n] = fmaf((float)a2, s, b);
    out[(size_t)(r0 + 3) * N_TOTAL + n] = fmaf((float)a3, s, b);
}

__global__ void __launch_bounds__(THREADS, 2)
qgemm_hmma_kernel(const float* __restrict__ scale_i, const float* __restrict__ scale_w,
                  const float* __restrict__ bias, float* __restrict__ out) {
    extern __shared__ char smem[];
    const uint16_t* __restrict__ x = g_xh;
    const uint16_t* __restrict__ w = g_wh;
    const uint32_t sbase = smem_u32(smem);
    const int tid = threadIdx.x;
    const int lane = tid & 31;
    const int wid = tid >> 5;
    const int warp_m = wid & 3;        // (HMMA warps) 4 along M
    const int warp_n = wid >> 2;       // 2 along N
    const int m0 = blockIdx.y * TILE_M;
    const int n0 = blockIdx.x * TILE_N;
    const int cta = blockIdx.y * GRID_X + blockIdx.x;   // 0..1855

    const int tg = lane >> 2;
    const int tc = lane & 3;
    const float si = __ldg(scale_i);

    float acc[2][8][4];
#pragma unroll
    for (int mt = 0; mt < 2; mt++)
#pragma unroll
        for (int nt = 0; nt < 8; nt++)
#pragma unroll
            for (int j = 0; j < 4; j++) acc[mt][nt][j] = 0.0f;

    const int am = lane >> 3;
    const uint32_t aOff = (uint32_t)(warp_m * 32 + (am & 1) * 8 + (lane & 7)) * ROW_B
                        + (uint32_t)(am >> 1) * 16;
    const uint32_t bOff = (uint32_t)((wid < 8 ? warp_n : 0) * 64 + (am >> 1) * 8 + (lane & 7)) * ROW_B
                        + (uint32_t)(am & 1) * 16;

    // Prologue: stages 0,1 in flight (dp4a warp commits empty groups)
    load_stage(x, w, m0, n0, 0, sbase, 0, tid); CP_COMMIT();
    load_stage(x, w, m0, n0, 1, sbase, 1, tid); CP_COMMIT();

#pragma unroll 1
    for (int kc = 0; kc < NCHUNK; kc++) {
        CP_WAIT1();
        __syncthreads();
        if (kc + 2 < NCHUNK)
            load_stage(x, w, m0, n0, kc + 2, sbase, (kc + 2) % NSTAGES, tid);
        CP_COMMIT();

        if (wid < 8) {
            // ---- HMMA: byte-identical schedule to the 202.6us baseline ----
            const int stage = kc % NSTAGES;
            const uint32_t aS = sbase + stage * A_STAGE + aOff;
            const uint32_t bS = sbase + SM_B0 + stage * B_STAGE + bOff;
#pragma unroll
            for (int ks = 0; ks < 4; ks++) {
                const uint32_t ko = ks * 32;
                uint32_t a00, a01, a02, a03, a10, a11, a12, a13;
                uint32_t e0, e1, e2, e3, o0, o1, o2, o3;
                LDSM4(a00, a01, a02, a03, aS + ko);
                LDSM4(a10, a11, a12, a13, aS + 16 * ROW_B + ko);
                LDSM4(e0, e1, e2, e3, bS + ko);
                LDSM4(o0, o1, o2, o3, bS + 16 * ROW_B + ko);
                MMA_F16(acc[0][0], a00, a01, a02, a03, e0, e1);
                MMA_F16(acc[1][0], a10, a11, a12, a13, e0, e1);
                MMA_F16(acc[0][1], a00, a01, a02, a03, e2, e3);
                MMA_F16(acc[1][1], a10, a11, a12, a13, e2, e3);
                LDSM4(e0, e1, e2, e3, bS + 32 * ROW_B + ko);
                MMA_F16(acc[0][2], a00, a01, a02, a03, o0, o1);
                MMA_F16(acc[1][2], a10, a11, a12, a13, o0, o1);
                MMA_F16(acc[0][3], a00, a01, a02, a03, o2, o3);
                MMA_F16(acc[1][3], a10, a11, a12, a13, o2, o3);
                LDSM4(o0, o1, o2, o3, bS + 48 * ROW_B + ko);
                MMA_F16(acc[0][4], a00, a01, a02, a03, e0, e1);
                MMA_F16(acc[1][4], a10, a11, a12, a13, e0, e1);
                MMA_F16(acc[0][5], a00, a01, a02, a03, e2, e3);
                MMA_F16(acc[1][5], a10, a11, a12, a13, e2, e3);
                MMA_F16(acc[0][6], a00, a01, a02, a03, o0, o1);
                MMA_F16(acc[1][6], a10, a11, a12, a13, o0, o1);
                MMA_F16(acc[0][7], a00, a01, a02, a03, o2, o3);
                MMA_F16(acc[1][7], a10, a11, a12, a13, o2, o3);
            }
        } else {
            // ---- dp4a sidecar: <=1 tile per sync slice (fits the window) ----
            const int t = cta + kc * NCTAS;
            if (t < DP_TILES)
                dp4a_tile(t, lane, si, scale_w, bias, out);
        }
    }

    // HMMA epilogue: out = acc * (scale_i * scale_w[n]) + bias[n]
    if (wid < 8) {
        const int row0 = m0 + warp_m * 32 + tg;
        const int col0 = n0 + warp_n * 64 + tc * 2;
#pragma unroll
        for (int nt = 0; nt < 8; nt++) {
            const int c = col0 + nt * 8;
            const float2 sw = __ldg(reinterpret_cast<const float2*>(scale_w + c));
            const float2 bb = __ldg(reinterpret_cast<const float2*>(bias + c));
            const float s0 = si * sw.x, s1 = si * sw.y;
#pragma unroll
            for (int mt = 0; mt < 2; mt++) {
                const int r = row0 + mt * 16;
                float2 v0, v1;
                v0.x = fmaf(acc[mt][nt][0], s0, bb.x);
                v0.y = fmaf(acc[mt][nt][1], s1, bb.y);
                v1.x = fmaf(acc[mt][nt][2], s0, bb.x);
                v1.y = fmaf(acc[mt][nt][3], s1, bb.y);
                *reinterpret_cast<float2*>(out + (size_t)r * N_TOTAL + c)       = v0;
                *reinterpret_cast<float2*>(out + (size_t)(r + 8) * N_TOTAL + c) = v1;
            }
        }
    }
}

extern "C" void kernel_launch(void* const* d_in, const int* in_sizes, int n_in,
                              void* d_out, int out_size) {
    // Harness promotes int8 jax arrays to int32 buffers.
    const int4* x32 = (const int4*)d_in[0];      // [8192,1024] int32 (int8 values)
    const int4* w32 = (const int4*)d_in[1];      // [4096,1024] int32
    const float* si = (const float*)d_in[2];     // scalar f32
    const float* sw = (const float*)d_in[3];     // [4096] f32
    const float* bi = (const float*)d_in[4];     // [4096] f32
    float* out = (float*)d_out;                  // [8192,4096] f32

    uint16_t *dxh = nullptr, *dwh = nullptr;
    int8_t *dw8 = nullptr, *dx8t = nullptr;
    cudaGetSymbolAddress((void**)&dxh, g_xh);
    cudaGetSymbolAddress((void**)&dwh, g_wh);
    cudaGetSymbolAddress((void**)&dw8, g_w8);
    cudaGetSymbolAddress((void**)&dx8t, g_x8t);

    {
        int n8x = (M_TOTAL * K_TOTAL) / 8;       // 1048576
        int n8w = (N_TOTAL * K_TOTAL) / 8;       // 524288
        int total = n8x + n8w;
        pack_both<<<(total + 255) / 256, 256>>>(x32, w32, dxh, dwh, dw8, dx8t, n8x, n8w);
    }

    cudaFuncSetAttribute(qgemm_hmma_kernel,
                         cudaFuncAttributeMaxDynamicSharedMemorySize, SM_BYTES);
    dim3 grid(GRID_X, GRID_Y);                   // (32, 58)
    qgemm_hmma_kernel<<<grid, THREADS, SM_BYTES, 0>>>(si, sw, bi, out);
}